// round 9
// baseline (speedup 1.0000x reference)
#include <cuda_runtime.h>
#include <cuda_fp16.h>
#include <cstdint>

// y = x @ W^T,  W[o,k] = scales[o,k/32] * (codes[o,k] - 128)
// R9: R8 mainloop (double-buffered ldmatrix frags, early wait+sync) with
// CTA 64x128 (4 warps of 32x64) -> 2048 CTAs -> 6.92 waves (tail ~1%),
// 4-stage cp.async pipeline (96KB smem, 2 CTA/SM).

#define IN_DIM   4096
#define OUT_DIM  4096
#define M_DIM    4096
#define NBLK_    128

#define BM       64
#define BN       128
#define BK       64
#define STAGES   4
#define THREADS  128
#define KITERS   (IN_DIM / BK)   // 64

__device__ __half g_xh[(size_t)M_DIM * IN_DIM];
__device__ __half g_wh[(size_t)OUT_DIM * IN_DIM];

#define A_STAGE_H   (BM * BK)                     // 4096 halves (8 KB)
#define B_STAGE_H   (BN * BK)                     // 8192 halves (16 KB)
#define B_BASE_H    (STAGES * A_STAGE_H)
#define SMEM_BYTES  ((STAGES * (A_STAGE_H + B_STAGE_H)) * 2)   // 98304

// ---------------- merged prepass ----------------
#define NX4 ((M_DIM * IN_DIM) / 4)
#define NW4 ((OUT_DIM * IN_DIM) / 4)

__global__ void prepass_kernel(const float4* __restrict__ x,
                               const float* __restrict__ scales,
                               const int4* __restrict__ codes) {
    int i = blockIdx.x * blockDim.x + threadIdx.x;
    if (i < NX4) {
        float4 v = x[i];
        __half2 h0 = __floats2half2_rn(v.x, v.y);
        __half2 h1 = __floats2half2_rn(v.z, v.w);
        uint2 u;
        u.x = *reinterpret_cast<uint32_t*>(&h0);
        u.y = *reinterpret_cast<uint32_t*>(&h1);
        reinterpret_cast<uint2*>(g_xh)[i] = u;
    } else if (i < NX4 + NW4) {
        int j = i - NX4;
        int gelt = j * 4;
        int o  = gelt >> 12;
        int kb = (gelt & 4095) >> 5;
        float s = __ldg(scales + o * NBLK_ + kb);
        int4 c = codes[j];
        __half2 h0 = __floats2half2_rn(s * (float)(c.x - 128), s * (float)(c.y - 128));
        __half2 h1 = __floats2half2_rn(s * (float)(c.z - 128), s * (float)(c.w - 128));
        uint2 u;
        u.x = *reinterpret_cast<uint32_t*>(&h0);
        u.y = *reinterpret_cast<uint32_t*>(&h1);
        reinterpret_cast<uint2*>(g_wh)[j] = u;
    }
}

// ---------------- GEMM helpers ----------------

__device__ __forceinline__ void cp_async16(uint32_t saddr, const void* g) {
    asm volatile("cp.async.cg.shared.global [%0], [%1], 16;" :: "r"(saddr), "l"(g));
}
__device__ __forceinline__ void cp_commit() {
    asm volatile("cp.async.commit_group;");
}
template <int N>
__device__ __forceinline__ void cp_wait() {
    asm volatile("cp.async.wait_group %0;" :: "n"(N));
}
__device__ __forceinline__ void ldsm_x4(uint32_t& r0, uint32_t& r1,
                                        uint32_t& r2, uint32_t& r3, uint32_t addr) {
    asm volatile("ldmatrix.sync.aligned.m8n8.x4.shared.b16 {%0,%1,%2,%3}, [%4];"
                 : "=r"(r0), "=r"(r1), "=r"(r2), "=r"(r3) : "r"(addr));
}
__device__ __forceinline__ void mma_f16(float* c, const uint32_t* a, const uint32_t* b) {
    asm volatile(
        "mma.sync.aligned.m16n8k16.row.col.f32.f16.f16.f32 "
        "{%0,%1,%2,%3}, {%4,%5,%6,%7}, {%8,%9}, {%0,%1,%2,%3};"
        : "+f"(c[0]), "+f"(c[1]), "+f"(c[2]), "+f"(c[3])
        : "r"(a[0]), "r"(a[1]), "r"(a[2]), "r"(a[3]), "r"(b[0]), "r"(b[1]));
}

__device__ __forceinline__ int tile_off(int row, int chunk) {
    return row * BK + ((chunk ^ (row & 7)) << 3);
}

__device__ __forceinline__ void load_stage(int kb, int st, int m0, int n0,
                                           int tid, uint32_t smem_u32) {
    const __half* gA = g_xh + (size_t)m0 * IN_DIM + kb * BK;
    const __half* gB = g_wh + (size_t)n0 * IN_DIM + kb * BK;
    uint32_t aBase = smem_u32 + (uint32_t)(st * A_STAGE_H) * 2;
    uint32_t bBase = smem_u32 + (uint32_t)(B_BASE_H + st * B_STAGE_H) * 2;
    #pragma unroll
    for (int it = 0; it < 4; it++) {       // A: 64 rows x 8 chunks = 512
        int idx = tid + it * THREADS;
        int row = idx >> 3, ch = idx & 7;
        cp_async16(aBase + (uint32_t)tile_off(row, ch) * 2,
                   gA + (size_t)row * IN_DIM + ch * 8);
    }
    #pragma unroll
    for (int it = 0; it < 8; it++) {       // B: 128 rows x 8 chunks = 1024
        int idx = tid + it * THREADS;
        int row = idx >> 3, ch = idx & 7;
        cp_async16(bBase + (uint32_t)tile_off(row, ch) * 2,
                   gB + (size_t)row * IN_DIM + ch * 8);
    }
}

struct Frag {
    uint32_t a[2][4];
    uint32_t b[8][2];
};

__global__ __launch_bounds__(THREADS, 2)
void gguf_hgemm7(float* __restrict__ y) {
    extern __shared__ __half sm[];
    uint32_t smem_u32 = (uint32_t)__cvta_generic_to_shared(sm);

    const int tid  = threadIdx.x;
    const int lane = tid & 31;
    const int wid  = tid >> 5;
    const int wm   = wid >> 1;     // 0..1 -> 32 m rows each
    const int wn   = wid & 1;      // 0..1 -> 64 n cols each

    const int m0 = blockIdx.y * BM;
    const int n0 = blockIdx.x * BN;

    float acc[2][8][4];
    #pragma unroll
    for (int i = 0; i < 2; i++)
        #pragma unroll
        for (int j = 0; j < 8; j++)
            #pragma unroll
            for (int v = 0; v < 4; v++) acc[i][j][v] = 0.0f;

    const int a_lr = lane & 15;
    const int a_lc = lane >> 4;
    const int b_lr = (lane & 7) + ((lane >> 4) << 3);
    const int b_lc = (lane >> 3) & 1;

    int rowA[2], rowB[4];
    #pragma unroll
    for (int mt = 0; mt < 2; mt++) rowA[mt] = wm * 32 + mt * 16 + a_lr;
    #pragma unroll
    for (int p = 0; p < 4; p++)    rowB[p]  = wn * 64 + p * 16 + b_lr;

    auto load_frags = [&](Frag& f, uint32_t aBase, uint32_t bBase, int ks) {
        const int ck0 = ks * 2;
        #pragma unroll
        for (int mt = 0; mt < 2; mt++) {
            int r = rowA[mt];
            uint32_t addr = aBase +
                (uint32_t)(r * BK + (((ck0 + a_lc) ^ (r & 7)) << 3)) * 2;
            ldsm_x4(f.a[mt][0], f.a[mt][1], f.a[mt][2], f.a[mt][3], addr);
        }
        #pragma unroll
        for (int p = 0; p < 4; p++) {
            int r = rowB[p];
            uint32_t addr = bBase +
                (uint32_t)(r * BK + (((ck0 + b_lc) ^ (r & 7)) << 3)) * 2;
            uint32_t r0, r1, r2, r3;
            ldsm_x4(r0, r1, r2, r3, addr);
            f.b[2 * p][0] = r0;     f.b[2 * p][1] = r1;
            f.b[2 * p + 1][0] = r2; f.b[2 * p + 1][1] = r3;
        }
    };

    auto stage_a = [&](int s) {
        return smem_u32 + (uint32_t)(s * A_STAGE_H) * 2;
    };
    auto stage_b = [&](int s) {
        return smem_u32 + (uint32_t)(B_BASE_H + s * B_STAGE_H) * 2;
    };

    // prologue: 3 stages in flight
    load_stage(0, 0, m0, n0, tid, smem_u32); cp_commit();
    load_stage(1, 1, m0, n0, tid, smem_u32); cp_commit();
    load_stage(2, 2, m0, n0, tid, smem_u32); cp_commit();
    cp_wait<2>();
    __syncthreads();

    Frag frag[2];
    load_frags(frag[0], stage_a(0), stage_b(0), 0);
    int fb = 0;

    int s = 0;
    for (int kb = 0; kb < KITERS; kb++) {
        const uint32_t aB = stage_a(s);
        const uint32_t bB = stage_b(s);
        const int sn = (s + 1 == STAGES) ? 0 : s + 1;

        #pragma unroll
        for (int ks = 0; ks < BK / 16; ks++) {
            const int nb = fb ^ 1;
            if (ks < BK / 16 - 1) {
                load_frags(frag[nb], aB, bB, ks + 1);
            } else {
                int nk = kb + 3;
                if (nk < KITERS) {
                    int s2 = (s + 3 >= STAGES) ? s + 3 - STAGES : s + 3;
                    load_stage(nk, s2, m0, n0, tid, smem_u32);
                }
                cp_commit();
                cp_wait<2>();      // stage kb+1 resident
                __syncthreads();
                if (kb + 1 < KITERS)
                    load_frags(frag[nb], stage_a(sn), stage_b(sn), 0);
            }
            #pragma unroll
            for (int mt = 0; mt < 2; mt++)
                #pragma unroll
                for (int nt = 0; nt < 8; nt++)
                    mma_f16(acc[mt][nt], frag[fb].a[mt], frag[fb].b[nt]);
            fb = nb;
        }

        s = sn;
    }

    // epilogue
    const int lrow_q = lane >> 2;
    const int lcol_q = lane & 3;
    const int mrow  = m0 + wm * 32 + lrow_q;
    const int ncol0 = n0 + wn * 64 + lcol_q * 2;
    #pragma unroll
    for (int mt = 0; mt < 2; mt++) {
        #pragma unroll
        for (int nt = 0; nt < 8; nt++) {
            int r = mrow + mt * 16;
            int c = ncol0 + nt * 8;
            float2 lo = make_float2(acc[mt][nt][0], acc[mt][nt][1]);
            float2 hi = make_float2(acc[mt][nt][2], acc[mt][nt][3]);
            *reinterpret_cast<float2*>(y + (size_t)r * OUT_DIM + c)       = lo;
            *reinterpret_cast<float2*>(y + (size_t)(r + 8) * OUT_DIM + c) = hi;
        }
    }
}

extern "C" void kernel_launch(void* const* d_in, const int* in_sizes, int n_in,
                              void* d_out, int out_size) {
    const float* x      = (const float*)d_in[0];
    const float* scales = (const float*)d_in[1];
    const int*   codes  = (const int*)d_in[2];
    float*       y      = (float*)d_out;

    cudaFuncSetAttribute(gguf_hgemm7, cudaFuncAttributeMaxDynamicSharedMemorySize,
                         SMEM_BYTES);

    int ntot = NX4 + NW4;
    prepass_kernel<<<(ntot + 255) / 256, 256>>>(
        reinterpret_cast<const float4*>(x), scales,
        reinterpret_cast<const int4*>(codes));

    dim3 grid(OUT_DIM / BN, M_DIM / BM);   // (32, 64) = 2048 CTAs
    gguf_hgemm7<<<grid, THREADS, SMEM_BYTES>>>(y);
}

// round 10
// speedup vs baseline: 1.0467x; 1.0467x over previous
#include <cuda_runtime.h>
#include <cuda_fp16.h>
#include <cstdint>

// y = x @ W^T,  W[o,k] = scales[o,k/32] * (codes[o,k] - 128)
// R10: R8 mainloop (CTA 128x128, 4 warps of 64x64, 3-stage cp.async,
// double-buffered ldmatrix frags, 2 CTA/SM) + remainder-wave split-K:
//   tiles 0..887   : full K (3.0 exact waves)
//   tiles 888..1023: split into 2 half-K CTAs each (272 CTAs, ~0.5 wave),
//                    partials to scratch, tiny combine kernel sums pairs.

#define IN_DIM   4096
#define OUT_DIM  4096
#define M_DIM    4096
#define NBLK_    128

#define BM       128
#define BN       128
#define BK       64
#define STAGES   3
#define THREADS  128
#define KITERS   (IN_DIM / BK)   // 64

#define NTILES   1024
#define SPLIT_T0 888             // first split tile
#define NSPLIT   (NTILES - SPLIT_T0)   // 136
#define GRID_CTAS (SPLIT_T0 + 2 * NSPLIT) // 1160

__device__ __half g_xh[(size_t)M_DIM * IN_DIM];
__device__ __half g_wh[(size_t)OUT_DIM * IN_DIM];
__device__ float  g_part[(size_t)2 * NSPLIT * BM * BN];   // 17.8 MB partials

#define A_STAGE_H   (BM * BK)                     // 8192 halves (16 KB)
#define B_STAGE_H   (BN * BK)
#define B_BASE_H    (STAGES * A_STAGE_H)
#define SMEM_BYTES  ((STAGES * (A_STAGE_H + B_STAGE_H)) * 2)   // 98304

// ---------------- merged prepass ----------------
#define NX4 ((M_DIM * IN_DIM) / 4)
#define NW4 ((OUT_DIM * IN_DIM) / 4)

__global__ void prepass_kernel(const float4* __restrict__ x,
                               const float* __restrict__ scales,
                               const int4* __restrict__ codes) {
    int i = blockIdx.x * blockDim.x + threadIdx.x;
    if (i < NX4) {
        float4 v = x[i];
        __half2 h0 = __floats2half2_rn(v.x, v.y);
        __half2 h1 = __floats2half2_rn(v.z, v.w);
        uint2 u;
        u.x = *reinterpret_cast<uint32_t*>(&h0);
        u.y = *reinterpret_cast<uint32_t*>(&h1);
        reinterpret_cast<uint2*>(g_xh)[i] = u;
    } else if (i < NX4 + NW4) {
        int j = i - NX4;
        int gelt = j * 4;
        int o  = gelt >> 12;
        int kb = (gelt & 4095) >> 5;
        float s = __ldg(scales + o * NBLK_ + kb);
        int4 c = codes[j];
        __half2 h0 = __floats2half2_rn(s * (float)(c.x - 128), s * (float)(c.y - 128));
        __half2 h1 = __floats2half2_rn(s * (float)(c.z - 128), s * (float)(c.w - 128));
        uint2 u;
        u.x = *reinterpret_cast<uint32_t*>(&h0);
        u.y = *reinterpret_cast<uint32_t*>(&h1);
        reinterpret_cast<uint2*>(g_wh)[j] = u;
    }
}

// ---------------- GEMM helpers ----------------

__device__ __forceinline__ void cp_async16(uint32_t saddr, const void* g) {
    asm volatile("cp.async.cg.shared.global [%0], [%1], 16;" :: "r"(saddr), "l"(g));
}
__device__ __forceinline__ void cp_commit() {
    asm volatile("cp.async.commit_group;");
}
template <int N>
__device__ __forceinline__ void cp_wait() {
    asm volatile("cp.async.wait_group %0;" :: "n"(N));
}
__device__ __forceinline__ void ldsm_x4(uint32_t& r0, uint32_t& r1,
                                        uint32_t& r2, uint32_t& r3, uint32_t addr) {
    asm volatile("ldmatrix.sync.aligned.m8n8.x4.shared.b16 {%0,%1,%2,%3}, [%4];"
                 : "=r"(r0), "=r"(r1), "=r"(r2), "=r"(r3) : "r"(addr));
}
__device__ __forceinline__ void mma_f16(float* c, const uint32_t* a, const uint32_t* b) {
    asm volatile(
        "mma.sync.aligned.m16n8k16.row.col.f32.f16.f16.f32 "
        "{%0,%1,%2,%3}, {%4,%5,%6,%7}, {%8,%9}, {%0,%1,%2,%3};"
        : "+f"(c[0]), "+f"(c[1]), "+f"(c[2]), "+f"(c[3])
        : "r"(a[0]), "r"(a[1]), "r"(a[2]), "r"(a[3]), "r"(b[0]), "r"(b[1]));
}

__device__ __forceinline__ int tile_off(int row, int chunk) {
    return row * BK + ((chunk ^ (row & 7)) << 3);
}

__device__ __forceinline__ void load_stage(int kb, int st, int m0, int n0,
                                           int tid, uint32_t smem_u32) {
    const __half* gA = g_xh + (size_t)m0 * IN_DIM + kb * BK;
    const __half* gB = g_wh + (size_t)n0 * IN_DIM + kb * BK;
    uint32_t aBase = smem_u32 + (uint32_t)(st * A_STAGE_H) * 2;
    uint32_t bBase = smem_u32 + (uint32_t)(B_BASE_H + st * B_STAGE_H) * 2;
    #pragma unroll
    for (int it = 0; it < 8; it++) {
        int idx = tid + it * THREADS;
        int row = idx >> 3, ch = idx & 7;
        cp_async16(aBase + (uint32_t)tile_off(row, ch) * 2,
                   gA + (size_t)row * IN_DIM + ch * 8);
    }
    #pragma unroll
    for (int it = 0; it < 8; it++) {
        int idx = tid + it * THREADS;
        int row = idx >> 3, ch = idx & 7;
        cp_async16(bBase + (uint32_t)tile_off(row, ch) * 2,
                   gB + (size_t)row * IN_DIM + ch * 8);
    }
}

struct Frag {
    uint32_t a[4][4];
    uint32_t b[8][2];
};

__global__ __launch_bounds__(THREADS, 2)
void gguf_hgemm8(float* __restrict__ y) {
    extern __shared__ __half sm[];
    uint32_t smem_u32 = (uint32_t)__cvta_generic_to_shared(sm);

    const int tid  = threadIdx.x;
    const int lane = tid & 31;
    const int wid  = tid >> 5;
    const int wm   = wid >> 1;     // 0..1 -> 64 m rows
    const int wn   = wid & 1;      // 0..1 -> 64 n cols

    // work assignment: full tiles vs half-K remainder tiles
    const int bid = blockIdx.x;
    int t, kb0, nkb;
    float* dst;
    int dstride;
    if (bid < SPLIT_T0) {
        t = bid; kb0 = 0; nkb = KITERS;
        dstride = OUT_DIM;
        dst = nullptr;   // set below after m0/n0
    } else {
        int idx = bid - SPLIT_T0;
        t = SPLIT_T0 + (idx >> 1);
        kb0 = (idx & 1) * (KITERS / 2);
        nkb = KITERS / 2;
        dstride = BN;
        dst = g_part + (size_t)idx * (BM * BN);
    }
    const int m0 = (t >> 5) * BM;
    const int n0 = (t & 31) * BN;
    if (bid < SPLIT_T0) dst = y + (size_t)m0 * OUT_DIM + n0;

    float acc[4][8][4];
    #pragma unroll
    for (int i = 0; i < 4; i++)
        #pragma unroll
        for (int j = 0; j < 8; j++)
            #pragma unroll
            for (int v = 0; v < 4; v++) acc[i][j][v] = 0.0f;

    const int a_lr = lane & 15;
    const int a_lc = lane >> 4;
    const int b_lr = (lane & 7) + ((lane >> 4) << 3);
    const int b_lc = (lane >> 3) & 1;

    int rowA[4], rowB[4];
    #pragma unroll
    for (int mt = 0; mt < 4; mt++) rowA[mt] = wm * 64 + mt * 16 + a_lr;
    #pragma unroll
    for (int p = 0; p < 4; p++)    rowB[p]  = wn * 64 + p * 16 + b_lr;

    auto load_frags = [&](Frag& f, uint32_t aBase, uint32_t bBase, int ks) {
        const int ck0 = ks * 2;
        #pragma unroll
        for (int mt = 0; mt < 4; mt++) {
            int r = rowA[mt];
            uint32_t addr = aBase +
                (uint32_t)(r * BK + (((ck0 + a_lc) ^ (r & 7)) << 3)) * 2;
            ldsm_x4(f.a[mt][0], f.a[mt][1], f.a[mt][2], f.a[mt][3], addr);
        }
        #pragma unroll
        for (int p = 0; p < 4; p++) {
            int r = rowB[p];
            uint32_t addr = bBase +
                (uint32_t)(r * BK + (((ck0 + b_lc) ^ (r & 7)) << 3)) * 2;
            uint32_t r0, r1, r2, r3;
            ldsm_x4(r0, r1, r2, r3, addr);
            f.b[2 * p][0] = r0;     f.b[2 * p][1] = r1;
            f.b[2 * p + 1][0] = r2; f.b[2 * p + 1][1] = r3;
        }
    };

    auto stage_a = [&](int s) {
        return smem_u32 + (uint32_t)(s * A_STAGE_H) * 2;
    };
    auto stage_b = [&](int s) {
        return smem_u32 + (uint32_t)(B_BASE_H + s * B_STAGE_H) * 2;
    };

    // prologue
    load_stage(kb0 + 0, 0, m0, n0, tid, smem_u32); cp_commit();
    load_stage(kb0 + 1, 1, m0, n0, tid, smem_u32); cp_commit();
    cp_wait<1>();
    __syncthreads();

    Frag frag[2];
    load_frags(frag[0], stage_a(0), stage_b(0), 0);
    int fb = 0;

    int s = 0;
    for (int lk = 0; lk < nkb; lk++) {
        const uint32_t aB = stage_a(s);
        const uint32_t bB = stage_b(s);
        const int sn = (s + 1 == STAGES) ? 0 : s + 1;

        #pragma unroll
        for (int ks = 0; ks < BK / 16; ks++) {
            const int nb = fb ^ 1;
            if (ks < BK / 16 - 1) {
                load_frags(frag[nb], aB, bB, ks + 1);
            } else {
                int nl = lk + 2;
                if (nl < nkb) {
                    int s2 = (s + 2 >= STAGES) ? s + 2 - STAGES : s + 2;
                    load_stage(kb0 + nl, s2, m0, n0, tid, smem_u32);
                }
                cp_commit();
                cp_wait<1>();
                __syncthreads();
                if (lk + 1 < nkb)
                    load_frags(frag[nb], stage_a(sn), stage_b(sn), 0);
            }
            #pragma unroll
            for (int mt = 0; mt < 4; mt++)
                #pragma unroll
                for (int nt = 0; nt < 8; nt++)
                    mma_f16(acc[mt][nt], frag[fb].a[mt], frag[fb].b[nt]);
            fb = nb;
        }

        s = sn;
    }

    // epilogue (local tile coords; dst/dstride select y vs partial buffer)
    const int lrow_q = lane >> 2;
    const int lcol_q = lane & 3;
    const int mrow  = wm * 64 + lrow_q;
    const int ncol0 = wn * 64 + lcol_q * 2;
    #pragma unroll
    for (int mt = 0; mt < 4; mt++) {
        #pragma unroll
        for (int nt = 0; nt < 8; nt++) {
            int r = mrow + mt * 16;
            int c = ncol0 + nt * 8;
            float2 lo = make_float2(acc[mt][nt][0], acc[mt][nt][1]);
            float2 hi = make_float2(acc[mt][nt][2], acc[mt][nt][3]);
            *reinterpret_cast<float2*>(dst + (size_t)r * dstride + c)       = lo;
            *reinterpret_cast<float2*>(dst + (size_t)(r + 8) * dstride + c) = hi;
        }
    }
}

// ---------------- combine partials ----------------
// 136 tiles * 16384 elems, float4-vectorized: y[tile] = part[2p] + part[2p+1]
#define COMB_V4 (NSPLIT * BM * BN / 4)     // 557056

__global__ void combine_kernel(float* __restrict__ y) {
    int j = blockIdx.x * blockDim.x + threadIdx.x;
    if (j >= COMB_V4) return;
    int p  = j >> 12;          // / 4096 : tile pair 0..135
    int e4 = j & 4095;         // float4 within tile
    const float4* pa = reinterpret_cast<const float4*>(g_part + (size_t)(2 * p) * (BM * BN));
    const float4* pb = reinterpret_cast<const float4*>(g_part + (size_t)(2 * p + 1) * (BM * BN));
    float4 a = pa[e4], b = pb[e4];
    a.x += b.x; a.y += b.y; a.z += b.z; a.w += b.w;
    int t = SPLIT_T0 + p;
    int e = e4 * 4;
    int r = e >> 7;            // row 0..127
    int c = e & 127;           // col (multiple of 4)
    *reinterpret_cast<float4*>(
        y + (size_t)((t >> 5) * BM + r) * OUT_DIM + (t & 31) * BN + c) = a;
}

extern "C" void kernel_launch(void* const* d_in, const int* in_sizes, int n_in,
                              void* d_out, int out_size) {
    const float* x      = (const float*)d_in[0];
    const float* scales = (const float*)d_in[1];
    const int*   codes  = (const int*)d_in[2];
    float*       y      = (float*)d_out;

    cudaFuncSetAttribute(gguf_hgemm8, cudaFuncAttributeMaxDynamicSharedMemorySize,
                         SMEM_BYTES);

    int ntot = NX4 + NW4;
    prepass_kernel<<<(ntot + 255) / 256, 256>>>(
        reinterpret_cast<const float4*>(x), scales,
        reinterpret_cast<const int4*>(codes));

    gguf_hgemm8<<<GRID_CTAS, THREADS, SMEM_BYTES>>>(y);

    combine_kernel<<<(COMB_V4 + 255) / 256, 256>>>(y);
}

// round 11
// speedup vs baseline: 1.0797x; 1.0315x over previous
#include <cuda_runtime.h>
#include <cuda_fp16.h>
#include <cstdint>

// y = x @ W^T,  W[o,k] = scales[o,k/32] * (codes[o,k] - 128)
// R11: R8 GEMM exactly (CTA 128x128, 4 warps of 64x64, 3-stage cp.async,
// double-buffered ldmatrix frags, 2 CTA/SM; split-K reverted) +
// MLP=4 prepass (4 independent quads per thread) + streaming epilogue.

#define IN_DIM   4096
#define OUT_DIM  4096
#define M_DIM    4096
#define NBLK_    128

#define BM       128
#define BN       128
#define BK       64
#define STAGES   3
#define THREADS  128
#define KITERS   (IN_DIM / BK)   // 64

__device__ __half g_xh[(size_t)M_DIM * IN_DIM];
__device__ __half g_wh[(size_t)OUT_DIM * IN_DIM];

#define A_STAGE_H   (BM * BK)                     // 8192 halves (16 KB)
#define B_STAGE_H   (BN * BK)
#define B_BASE_H    (STAGES * A_STAGE_H)
#define SMEM_BYTES  ((STAGES * (A_STAGE_H + B_STAGE_H)) * 2)   // 98304

// ---------------- prepass: MLP=4 ----------------
#define NX4 ((M_DIM * IN_DIM) / 4)       // 4M quads
#define NW4 ((OUT_DIM * IN_DIM) / 4)
#define PRE_T    256
#define PRE_C    4
#define PRE_XBLK (NX4 / (PRE_T * PRE_C))  // 4096
#define PRE_WBLK (NW4 / (PRE_T * PRE_C))  // 4096

__global__ void prepass_kernel(const float4* __restrict__ x,
                               const float* __restrict__ scales,
                               const int4* __restrict__ codes) {
    int b = blockIdx.x;
    if (b < PRE_XBLK) {
        int base = b * (PRE_T * PRE_C) + threadIdx.x;
        float4 v[PRE_C];
        #pragma unroll
        for (int j = 0; j < PRE_C; j++) v[j] = x[base + j * PRE_T];
        #pragma unroll
        for (int j = 0; j < PRE_C; j++) {
            __half2 h0 = __floats2half2_rn(v[j].x, v[j].y);
            __half2 h1 = __floats2half2_rn(v[j].z, v[j].w);
            uint2 u;
            u.x = *reinterpret_cast<uint32_t*>(&h0);
            u.y = *reinterpret_cast<uint32_t*>(&h1);
            reinterpret_cast<uint2*>(g_xh)[base + j * PRE_T] = u;
        }
    } else {
        int base = (b - PRE_XBLK) * (PRE_T * PRE_C) + threadIdx.x;
        int4 c[PRE_C];
        float s[PRE_C];
        #pragma unroll
        for (int j = 0; j < PRE_C; j++) {
            int idx = base + j * PRE_T;
            c[j] = codes[idx];
            int gelt = idx * 4;
            s[j] = __ldg(scales + (gelt >> 12) * NBLK_ + ((gelt & 4095) >> 5));
        }
        #pragma unroll
        for (int j = 0; j < PRE_C; j++) {
            __half2 h0 = __floats2half2_rn(s[j] * (float)(c[j].x - 128),
                                           s[j] * (float)(c[j].y - 128));
            __half2 h1 = __floats2half2_rn(s[j] * (float)(c[j].z - 128),
                                           s[j] * (float)(c[j].w - 128));
            uint2 u;
            u.x = *reinterpret_cast<uint32_t*>(&h0);
            u.y = *reinterpret_cast<uint32_t*>(&h1);
            reinterpret_cast<uint2*>(g_wh)[base + j * PRE_T] = u;
        }
    }
}

// ---------------- GEMM helpers ----------------

__device__ __forceinline__ void cp_async16(uint32_t saddr, const void* g) {
    asm volatile("cp.async.cg.shared.global [%0], [%1], 16;" :: "r"(saddr), "l"(g));
}
__device__ __forceinline__ void cp_commit() {
    asm volatile("cp.async.commit_group;");
}
template <int N>
__device__ __forceinline__ void cp_wait() {
    asm volatile("cp.async.wait_group %0;" :: "n"(N));
}
__device__ __forceinline__ void ldsm_x4(uint32_t& r0, uint32_t& r1,
                                        uint32_t& r2, uint32_t& r3, uint32_t addr) {
    asm volatile("ldmatrix.sync.aligned.m8n8.x4.shared.b16 {%0,%1,%2,%3}, [%4];"
                 : "=r"(r0), "=r"(r1), "=r"(r2), "=r"(r3) : "r"(addr));
}
__device__ __forceinline__ void mma_f16(float* c, const uint32_t* a, const uint32_t* b) {
    asm volatile(
        "mma.sync.aligned.m16n8k16.row.col.f32.f16.f16.f32 "
        "{%0,%1,%2,%3}, {%4,%5,%6,%7}, {%8,%9}, {%0,%1,%2,%3};"
        : "+f"(c[0]), "+f"(c[1]), "+f"(c[2]), "+f"(c[3])
        : "r"(a[0]), "r"(a[1]), "r"(a[2]), "r"(a[3]), "r"(b[0]), "r"(b[1]));
}

__device__ __forceinline__ int tile_off(int row, int chunk) {
    return row * BK + ((chunk ^ (row & 7)) << 3);
}

__device__ __forceinline__ void load_stage(int kb, int st, int m0, int n0,
                                           int tid, uint32_t smem_u32) {
    const __half* gA = g_xh + (size_t)m0 * IN_DIM + kb * BK;
    const __half* gB = g_wh + (size_t)n0 * IN_DIM + kb * BK;
    uint32_t aBase = smem_u32 + (uint32_t)(st * A_STAGE_H) * 2;
    uint32_t bBase = smem_u32 + (uint32_t)(B_BASE_H + st * B_STAGE_H) * 2;
    #pragma unroll
    for (int it = 0; it < 8; it++) {
        int idx = tid + it * THREADS;
        int row = idx >> 3, ch = idx & 7;
        cp_async16(aBase + (uint32_t)tile_off(row, ch) * 2,
                   gA + (size_t)row * IN_DIM + ch * 8);
    }
    #pragma unroll
    for (int it = 0; it < 8; it++) {
        int idx = tid + it * THREADS;
        int row = idx >> 3, ch = idx & 7;
        cp_async16(bBase + (uint32_t)tile_off(row, ch) * 2,
                   gB + (size_t)row * IN_DIM + ch * 8);
    }
}

struct Frag {
    uint32_t a[4][4];
    uint32_t b[8][2];
};

__global__ __launch_bounds__(THREADS, 2)
void gguf_hgemm9(float* __restrict__ y) {
    extern __shared__ __half sm[];
    uint32_t smem_u32 = (uint32_t)__cvta_generic_to_shared(sm);

    const int tid  = threadIdx.x;
    const int lane = tid & 31;
    const int wid  = tid >> 5;
    const int wm   = wid >> 1;     // 0..1 -> 64 m rows
    const int wn   = wid & 1;      // 0..1 -> 64 n cols

    const int m0 = blockIdx.y * BM;
    const int n0 = blockIdx.x * BN;

    float acc[4][8][4];
    #pragma unroll
    for (int i = 0; i < 4; i++)
        #pragma unroll
        for (int j = 0; j < 8; j++)
            #pragma unroll
            for (int v = 0; v < 4; v++) acc[i][j][v] = 0.0f;

    const int a_lr = lane & 15;
    const int a_lc = lane >> 4;
    const int b_lr = (lane & 7) + ((lane >> 4) << 3);
    const int b_lc = (lane >> 3) & 1;

    int rowA[4], rowB[4];
    #pragma unroll
    for (int mt = 0; mt < 4; mt++) rowA[mt] = wm * 64 + mt * 16 + a_lr;
    #pragma unroll
    for (int p = 0; p < 4; p++)    rowB[p]  = wn * 64 + p * 16 + b_lr;

    auto load_frags = [&](Frag& f, uint32_t aBase, uint32_t bBase, int ks) {
        const int ck0 = ks * 2;
        #pragma unroll
        for (int mt = 0; mt < 4; mt++) {
            int r = rowA[mt];
            uint32_t addr = aBase +
                (uint32_t)(r * BK + (((ck0 + a_lc) ^ (r & 7)) << 3)) * 2;
            ldsm_x4(f.a[mt][0], f.a[mt][1], f.a[mt][2], f.a[mt][3], addr);
        }
        #pragma unroll
        for (int p = 0; p < 4; p++) {
            int r = rowB[p];
            uint32_t addr = bBase +
                (uint32_t)(r * BK + (((ck0 + b_lc) ^ (r & 7)) << 3)) * 2;
            uint32_t r0, r1, r2, r3;
            ldsm_x4(r0, r1, r2, r3, addr);
            f.b[2 * p][0] = r0;     f.b[2 * p][1] = r1;
            f.b[2 * p + 1][0] = r2; f.b[2 * p + 1][1] = r3;
        }
    };

    auto stage_a = [&](int s) {
        return smem_u32 + (uint32_t)(s * A_STAGE_H) * 2;
    };
    auto stage_b = [&](int s) {
        return smem_u32 + (uint32_t)(B_BASE_H + s * B_STAGE_H) * 2;
    };

    // prologue
    load_stage(0, 0, m0, n0, tid, smem_u32); cp_commit();
    load_stage(1, 1, m0, n0, tid, smem_u32); cp_commit();
    cp_wait<1>();
    __syncthreads();

    Frag frag[2];
    load_frags(frag[0], stage_a(0), stage_b(0), 0);
    int fb = 0;

    int s = 0;
    for (int kb = 0; kb < KITERS; kb++) {
        const uint32_t aB = stage_a(s);
        const uint32_t bB = stage_b(s);
        const int sn = (s + 1 == STAGES) ? 0 : s + 1;

        #pragma unroll
        for (int ks = 0; ks < BK / 16; ks++) {
            const int nb = fb ^ 1;
            if (ks < BK / 16 - 1) {
                load_frags(frag[nb], aB, bB, ks + 1);
            } else {
                int nk = kb + 2;
                if (nk < KITERS) {
                    int s2 = (s + 2 >= STAGES) ? s + 2 - STAGES : s + 2;
                    load_stage(nk, s2, m0, n0, tid, smem_u32);
                }
                cp_commit();
                cp_wait<1>();
                __syncthreads();
                if (kb + 1 < KITERS)
                    load_frags(frag[nb], stage_a(sn), stage_b(sn), 0);
            }
            #pragma unroll
            for (int mt = 0; mt < 4; mt++)
                #pragma unroll
                for (int nt = 0; nt < 8; nt++)
                    mma_f16(acc[mt][nt], frag[fb].a[mt], frag[fb].b[nt]);
            fb = nb;
        }

        s = sn;
    }

    // epilogue: streaming stores (y is write-once; keep L2 for A/B tiles)
    const int lrow_q = lane >> 2;
    const int lcol_q = lane & 3;
    const int mrow  = m0 + wm * 64 + lrow_q;
    const int ncol0 = n0 + wn * 64 + lcol_q * 2;
    #pragma unroll
    for (int mt = 0; mt < 4; mt++) {
        #pragma unroll
        for (int nt = 0; nt < 8; nt++) {
            int r = mrow + mt * 16;
            int c = ncol0 + nt * 8;
            float2 lo = make_float2(acc[mt][nt][0], acc[mt][nt][1]);
            float2 hi = make_float2(acc[mt][nt][2], acc[mt][nt][3]);
            __stcs(reinterpret_cast<float2*>(y + (size_t)r * OUT_DIM + c), lo);
            __stcs(reinterpret_cast<float2*>(y + (size_t)(r + 8) * OUT_DIM + c), hi);
        }
    }
}

extern "C" void kernel_launch(void* const* d_in, const int* in_sizes, int n_in,
                              void* d_out, int out_size) {
    const float* x      = (const float*)d_in[0];
    const float* scales = (const float*)d_in[1];
    const int*   codes  = (const int*)d_in[2];
    float*       y      = (float*)d_out;

    cudaFuncSetAttribute(gguf_hgemm9, cudaFuncAttributeMaxDynamicSharedMemorySize,
                         SMEM_BYTES);

    prepass_kernel<<<PRE_XBLK + PRE_WBLK, PRE_T>>>(
        reinterpret_cast<const float4*>(x), scales,
        reinterpret_cast<const int4*>(codes));

    dim3 grid(OUT_DIM / BN, M_DIM / BM);   // (32, 32)
    gguf_hgemm9<<<grid, THREADS, SMEM_BYTES>>>(y);
}